// round 16
// baseline (speedup 1.0000x reference)
#include <cuda_runtime.h>
#include <cuda_fp16.h>
#include <cstdint>

#define DINL __device__ __forceinline__

// ---------------- problem constants ----------------
#define BATCH   8192
#define HID     512
#define NCOLS   2048            // 4 gates * 512, col n = 4*j + g  (g: 0=f,1=i,2=g,3=o)
#define KTOT    1024            // x(512) | h(512)

// ---------------- GEMM tiling ----------------
#define BM      128
#define BN      256
#define BK      64              // 64 halves = 128 B = one swizzled row
#define STAGES  4
#define KITERS  (KTOT / BK)     // 16
#define THREADS 256

#define A_ST_BYTES (BM * BK * 2)    // 16384
#define B_ST_BYTES (BN * BK * 2)    // 32768
#define SMEM_A     0
#define SMEM_B     (STAGES * A_ST_BYTES)                 // 65536
#define SMEM_BIAS  (SMEM_B + STAGES * B_ST_BYTES)        // 196608
#define SMEM_TOTAL (SMEM_BIAS + BN * 4)                  // 197632

// ---------------- device scratch ----------------
__device__ __half g_Bph[(size_t)NCOLS * KTOT];   // fp16 weights, [n][k] row-major, gate-interleaved
__device__ __half g_Ah[(size_t)BATCH * KTOT];    // fp16 activations, [b][k] = x||h
__device__ float  g_bias[NCOLS];                 // combined bias bx+bh, gate-interleaved

// ---------------- PTX helpers ----------------
DINL uint32_t smem_u32(const void* p) {
    uint32_t a;
    asm("{ .reg .u64 t; cvta.to.shared.u64 t, %1; cvt.u32.u64 %0, t; }" : "=r"(a) : "l"(p));
    return a;
}
// pack two fp32 -> fp16x2 in a b32 register (lo in low half)
DINL uint32_t pack_h2(float lo, float hi) {
    uint32_t r;
    asm("cvt.rn.f16x2.f32 %0, %1, %2;" : "=r"(r) : "f"(hi), "f"(lo));
    return r;
}
DINL void cp_async16(uint32_t d, const void* s) {
    asm volatile("cp.async.cg.shared.global [%0], [%1], 16;" :: "r"(d), "l"(s) : "memory");
}
DINL void cp_commit() { asm volatile("cp.async.commit_group;" ::: "memory"); }
template <int N> DINL void cp_wait() { asm volatile("cp.async.wait_group %0;" :: "n"(N) : "memory"); }

DINL void ldsm4(uint32_t addr, uint32_t* r) {
    asm volatile("ldmatrix.sync.aligned.m8n8.x4.shared.b16 {%0, %1, %2, %3}, [%4];"
                 : "=r"(r[0]), "=r"(r[1]), "=r"(r[2]), "=r"(r[3]) : "r"(addr));
}
// fp16 MMA, k16, fp32 accumulate
DINL void mma16(float* d, const uint32_t* a, const uint32_t* b) {
    asm volatile(
        "mma.sync.aligned.m16n8k16.row.col.f32.f16.f16.f32 "
        "{%0, %1, %2, %3}, {%4, %5, %6, %7}, {%8, %9}, {%0, %1, %2, %3};"
        : "+f"(d[0]), "+f"(d[1]), "+f"(d[2]), "+f"(d[3])
        : "r"(a[0]), "r"(a[1]), "r"(a[2]), "r"(a[3]), "r"(b[0]), "r"(b[1]));
}

DINL uint32_t swz(uint32_t off) { return off ^ ((off >> 3) & 0x70); }   // 16B-chunk xor row%8

DINL float sigm_(float x) { return __fdividef(1.0f, 1.0f + __expf(-x)); }
DINL float tanh_(float x) { return 1.0f - __fdividef(2.0f, __expf(2.0f * x) + 1.0f); }

// ---------------- prep: weights (gate-interleave) + activations -> fp16 ----------------
#define WCHUNKS (NCOLS * KTOT / 8)      // 262144 8-half chunks
#define ACHUNKS (BATCH * KTOT / 8)      // 1048576
#define PREP_BLOCKS ((WCHUNKS + ACHUNKS) / 256)   // 5120

__global__ void __launch_bounds__(256) prep_kernel(
    const float* __restrict__ x, const float* __restrict__ h,
    const float* __restrict__ Wfx, const float* __restrict__ Wfh,
    const float* __restrict__ Wix, const float* __restrict__ Wih,
    const float* __restrict__ Wgx, const float* __restrict__ Wgh,
    const float* __restrict__ Wox, const float* __restrict__ Woh,
    const float* __restrict__ bfx, const float* __restrict__ bfh,
    const float* __restrict__ bix, const float* __restrict__ bih,
    const float* __restrict__ bgx, const float* __restrict__ bgh,
    const float* __restrict__ box_, const float* __restrict__ boh)
{
    const size_t q = (size_t)blockIdx.x * 256 + threadIdx.x;
    const float* s;
    __half* dst;
    if (q < WCHUNKS) {
        const int n = (int)(q >> 7), c = (int)(q & 127);   // row, 8-half chunk
        const int g = n & 3, j = n >> 2;
        const float *wx, *wh, *bx, *bh;
        if      (g == 0) { wx = Wfx; wh = Wfh; bx = bfx;  bh = bfh; }
        else if (g == 1) { wx = Wix; wh = Wih; bx = bix;  bh = bih; }
        else if (g == 2) { wx = Wgx; wh = Wgh; bx = bgx;  bh = bgh; }
        else             { wx = Wox; wh = Woh; bx = box_; bh = boh; }
        s = (c < 64) ? (wx + (size_t)j * 512 + c * 8)
                     : (wh + (size_t)j * 512 + (c - 64) * 8);
        dst = g_Bph + q * 8;
        if (c == 0) g_bias[n] = bx[j] + bh[j];
    } else {
        const size_t qa = q - WCHUNKS;
        const int row = (int)(qa >> 7), c = (int)(qa & 127);
        s = (c < 64) ? (x + (size_t)row * 512 + c * 8)
                     : (h + (size_t)row * 512 + (c - 64) * 8);
        dst = g_Ah + qa * 8;
    }
    const float4 v0 = *(const float4*)(s);
    const float4 v1 = *(const float4*)(s + 4);
    uint4 o;
    o.x = pack_h2(v0.x, v0.y);
    o.y = pack_h2(v0.z, v0.w);
    o.z = pack_h2(v1.x, v1.y);
    o.w = pack_h2(v1.z, v1.w);
    *(uint4*)dst = o;
}

// ---------------- stage loaders (both via cp.async) ----------------
DINL void cp_A(uint32_t sb, int it, int m0, int tid)
{
    const uint32_t a_st = sb + SMEM_A + (it % STAGES) * A_ST_BYTES;
    const int kg = it * BK;
    #pragma unroll
    for (int i = 0; i < 4; i++) {
        const int q = tid + i * THREADS;     // 0..1023 (128 rows x 8 chunks)
        const int r = q >> 3, c = q & 7;
        const uint32_t d = a_st + swz((uint32_t)(r * 128 + c * 16));
        cp_async16(d, g_Ah + (size_t)(m0 + r) * KTOT + kg + c * 8);
    }
}
DINL void cp_B(uint32_t sb, int it, int n0, int tid)
{
    const uint32_t b_st = sb + SMEM_B + (it % STAGES) * B_ST_BYTES;
    const int kg = it * BK;
    #pragma unroll
    for (int i = 0; i < 8; i++) {
        const int q = tid + i * THREADS;     // 0..2047 (256 rows x 8 chunks)
        const int r = q >> 3, c = q & 7;
        const uint32_t d = b_st + swz((uint32_t)(r * 128 + c * 16));
        cp_async16(d, g_Bph + (size_t)(n0 + r) * KTOT + kg + c * 8);
    }
}

// ---------------- main fused kernel: 8 warps, warp tile 64x64, occ 1 ----------------
__global__ void __launch_bounds__(THREADS, 1) lstm_mma_kernel(
    const float* __restrict__ c_tm1, float* __restrict__ out)
{
    extern __shared__ __align__(1024) char smem[];
    const uint32_t sb = smem_u32(smem);
    const int tid  = threadIdx.x;
    const int lane = tid & 31, wid = tid >> 5;
    const int m0 = blockIdx.y * BM;
    const int n0 = blockIdx.x * BN;
    const int wm = wid >> 2, wn = wid & 3;   // warp grid 2(M) x 4(N), warp tile 64x64

    float* bias_s = (float*)(smem + SMEM_BIAS);
    bias_s[tid] = g_bias[n0 + tid];

    // ldmatrix per-lane patterns (layouts verified passing in R12/R13).
    const int sub = lane >> 3, ri = lane & 7;
    const int arow = (sub & 1) * 8 + ri;
    const int achk = sub >> 1;               // 16B chunk within a k16 slice
    const int brow = (sub >> 1) * 8 + ri;
    const int bchk = sub & 1;

    float acc[4][8][4];
    #pragma unroll
    for (int a = 0; a < 4; a++)
        #pragma unroll
        for (int b = 0; b < 8; b++)
            #pragma unroll
            for (int c = 0; c < 4; c++) acc[a][b][c] = 0.0f;

    // prologue: stages 0..2 via cp.async
    cp_A(sb, 0, m0, tid); cp_B(sb, 0, n0, tid); cp_commit();
    cp_A(sb, 1, m0, tid); cp_B(sb, 1, n0, tid); cp_commit();
    cp_A(sb, 2, m0, tid); cp_B(sb, 2, n0, tid); cp_commit();

    for (int it = 0; it < KITERS; ++it) {
        cp_wait<2>();
        __syncthreads();                  // A(it)+B(it) resident & visible

        const uint32_t a_st = sb + SMEM_A + (it % STAGES) * A_ST_BYTES;
        const uint32_t b_st = sb + SMEM_B + (it % STAGES) * B_ST_BYTES;

        // ks=0 LDSM addresses; per-ks address = addr0 ^ (ks<<5).
        uint32_t aaddr0[4], baddr0[4];
        #pragma unroll
        for (int mt = 0; mt < 4; mt++) {
            const int row = wm * 64 + mt * 16 + arow;
            aaddr0[mt] = a_st + (uint32_t)row * 128 +
                         ((uint32_t)(achk ^ (row & 7)) << 4);
        }
        #pragma unroll
        for (int nt2 = 0; nt2 < 4; nt2++) {
            const int row = wn * 64 + nt2 * 16 + brow;
            baddr0[nt2] = b_st + (uint32_t)row * 128 +
                          ((uint32_t)(bchk ^ (row & 7)) << 4);
        }

        // register-double-buffered fragments: load ks+1 while computing ks
        uint32_t af[2][4][4], bf[2][4][4];
        #pragma unroll
        for (int mt = 0; mt < 4; mt++) ldsm4(aaddr0[mt], af[0][mt]);
        #pragma unroll
        for (int nt2 = 0; nt2 < 4; nt2++) ldsm4(baddr0[nt2], bf[0][nt2]);

        #pragma unroll
        for (int ks = 0; ks < 4; ks++) {  // 4 x k16 = BK=64
            const int cur = ks & 1, nxt = cur ^ 1;
            if (ks < 3) {
                const uint32_t kx = (uint32_t)(ks + 1) << 5;
                #pragma unroll
                for (int mt = 0; mt < 4; mt++) ldsm4(aaddr0[mt] ^ kx, af[nxt][mt]);
                #pragma unroll
                for (int nt2 = 0; nt2 < 4; nt2++) ldsm4(baddr0[nt2] ^ kx, bf[nxt][nt2]);
            }
            if (ks == 0) {                // hide cp issue under the MMA block
                if (it + 3 < KITERS) { cp_A(sb, it + 3, m0, tid); cp_B(sb, it + 3, n0, tid); }
                cp_commit();              // one group per iteration (possibly empty)
            }
            #pragma unroll
            for (int mt = 0; mt < 4; mt++)
                #pragma unroll
                for (int nt = 0; nt < 8; nt++)
                    mma16(acc[mt][nt], af[cur][mt], bf[cur][nt >> 1] + (nt & 1) * 2);
        }
    }

    // -------- fused LSTM epilogue on register accumulators --------
    // c-frag: c0,c1 = (row g, cols 2*t4, 2*t4+1); c2,c3 = (row g+8, same cols).
    // Gate-interleaved cols: even t4 holds (f,i), odd t4 holds (g,o) of the same j;
    // lane^1 exchange gives each lane all 4 gates. Even lane stores h_t, odd stores c_t.
    float* h_out = out;
    float* c_out = out + (size_t)BATCH * HID;
    const int t4 = lane & 3, g = lane >> 2;
    const bool even = (t4 & 1) == 0;

    #pragma unroll
    for (int mt = 0; mt < 4; ++mt) {
        const int r1 = m0 + wm * 64 + mt * 16 + g;
        const int r2 = r1 + 8;
        #pragma unroll
        for (int nt = 0; nt < 8; ++nt) {
            const int nl = wn * 64 + nt * 8;
            const int col0 = nl + 2 * t4;
            const float p0 = acc[mt][nt][0] + bias_s[col0];
            const float p1 = acc[mt][nt][1] + bias_s[col0 + 1];
            const float p2 = acc[mt][nt][2] + bias_s[col0];
            const float p3 = acc[mt][nt][3] + bias_s[col0 + 1];
            const float q0 = __shfl_xor_sync(0xffffffffu, p0, 1);
            const float q1 = __shfl_xor_sync(0xffffffffu, p1, 1);
            const float q2 = __shfl_xor_sync(0xffffffffu, p2, 1);
            const float q3 = __shfl_xor_sync(0xffffffffu, p3, 1);
            const float fr1 = even ? p0 : q0, ir1 = even ? p1 : q1;
            const float gr1 = even ? q0 : p0, or1 = even ? q1 : p1;
            const float fr2 = even ? p2 : q2, ir2 = even ? p3 : q3;
            const float gr2 = even ? q2 : p2, or2 = even ? q3 : p3;

            const int j = (n0 + nl + ((t4 >> 1) << 2)) >> 2;
            const float cp1 = c_tm1[(size_t)r1 * HID + j];
            const float cp2 = c_tm1[(size_t)r2 * HID + j];
            const float cn1 = sigm_(fr1) * cp1 + sigm_(ir1) * tanh_(gr1);
            const float cn2 = sigm_(fr2) * cp2 + sigm_(ir2) * tanh_(gr2);
            const float hn1 = sigm_(or1) * tanh_(cn1);
            const float hn2 = sigm_(or2) * tanh_(cn2);
            if (even) {
                h_out[(size_t)r1 * HID + j] = hn1;
                h_out[(size_t)r2 * HID + j] = hn2;
            } else {
                c_out[(size_t)r1 * HID + j] = cn1;
                c_out[(size_t)r2 * HID + j] = cn2;
            }
        }
    }
}

// ---------------- launcher ----------------
extern "C" void kernel_launch(void* const* d_in, const int* in_sizes, int n_in,
                              void* d_out, int out_size)
{
    const float* x    = (const float*)d_in[0];
    const float* h    = (const float*)d_in[1];
    const float* c    = (const float*)d_in[2];
    const float* Wfx  = (const float*)d_in[3];
    const float* bfx  = (const float*)d_in[4];
    const float* Wfh  = (const float*)d_in[5];
    const float* bfh  = (const float*)d_in[6];
    const float* Wix  = (const float*)d_in[7];
    const float* bix  = (const float*)d_in[8];
    const float* Wih  = (const float*)d_in[9];
    const float* bih  = (const float*)d_in[10];
    const float* Wgx  = (const float*)d_in[11];
    const float* bgx  = (const float*)d_in[12];
    const float* Wgh  = (const float*)d_in[13];
    const float* bgh  = (const float*)d_in[14];
    const float* Wox  = (const float*)d_in[15];
    const float* box_ = (const float*)d_in[16];
    const float* Woh  = (const float*)d_in[17];
    const float* boh  = (const float*)d_in[18];

    cudaFuncSetAttribute(lstm_mma_kernel,
                         cudaFuncAttributeMaxDynamicSharedMemorySize, SMEM_TOTAL);

    prep_kernel<<<PREP_BLOCKS, 256>>>(x, h,
                                      Wfx, Wfh, Wix, Wih, Wgx, Wgh, Wox, Woh,
                                      bfx, bfh, bix, bih, bgx, bgh, box_, boh);

    dim3 grid(NCOLS / BN, BATCH / BM);   // (8, 64)
    lstm_mma_kernel<<<grid, THREADS, SMEM_TOTAL>>>(c, (float*)d_out);
}

// round 17
// speedup vs baseline: 1.2770x; 1.2770x over previous
#include <cuda_runtime.h>
#include <cuda_fp16.h>
#include <cstdint>

#define DINL __device__ __forceinline__

// ---------------- problem constants ----------------
#define BATCH   8192
#define HID     512
#define NCOLS   2048            // 4 gates * 512, col n = 4*j + g  (g: 0=f,1=i,2=g,3=o)
#define KTOT    1024            // x(512) | h(512)

// ---------------- GEMM tiling (R13 config: RF-optimal, 16 warps/SM) ----------------
#define BM      128
#define BN      128
#define BK      64              // 64 halves = 128 B = one swizzled row
#define STAGES  3
#define KITERS  (KTOT / BK)     // 16
#define THREADS 256

#define A_ST_BYTES (BM * BK * 2)    // 16384
#define B_ST_BYTES (BN * BK * 2)    // 16384
#define SMEM_A     0
#define SMEM_B     (STAGES * A_ST_BYTES)                 // 49152
#define SMEM_BIAS  (SMEM_B + STAGES * B_ST_BYTES)        // 98304
#define SMEM_TOTAL (SMEM_BIAS + BN * 4)                  // 98816

// ---------------- device scratch ----------------
__device__ __half g_Bph[(size_t)NCOLS * KTOT];   // fp16 weights, [n][k] row-major, gate-interleaved
__device__ __half g_Ah[(size_t)BATCH * KTOT];    // fp16 activations, [b][k] = x||h
__device__ float  g_bias[NCOLS];                 // combined bias bx+bh, gate-interleaved

// ---------------- PTX helpers ----------------
DINL uint32_t smem_u32(const void* p) {
    uint32_t a;
    asm("{ .reg .u64 t; cvta.to.shared.u64 t, %1; cvt.u32.u64 %0, t; }" : "=r"(a) : "l"(p));
    return a;
}
// pack two fp32 -> fp16x2 in a b32 register (lo in low half)
DINL uint32_t pack_h2(float lo, float hi) {
    uint32_t r;
    asm("cvt.rn.f16x2.f32 %0, %1, %2;" : "=r"(r) : "f"(hi), "f"(lo));
    return r;
}
DINL void cp_async16(uint32_t d, const void* s) {
    asm volatile("cp.async.cg.shared.global [%0], [%1], 16;" :: "r"(d), "l"(s) : "memory");
}
DINL void cp_commit() { asm volatile("cp.async.commit_group;" ::: "memory"); }
template <int N> DINL void cp_wait() { asm volatile("cp.async.wait_group %0;" :: "n"(N) : "memory"); }
DINL void prefetch_l2(const void* p) {
    asm volatile("prefetch.global.L2 [%0];" :: "l"(p));
}

DINL void ldsm4(uint32_t addr, uint32_t* r) {
    asm volatile("ldmatrix.sync.aligned.m8n8.x4.shared.b16 {%0, %1, %2, %3}, [%4];"
                 : "=r"(r[0]), "=r"(r[1]), "=r"(r[2]), "=r"(r[3]) : "r"(addr));
}
// fp16 MMA, k16, fp32 accumulate
DINL void mma16(float* d, const uint32_t* a, const uint32_t* b) {
    asm volatile(
        "mma.sync.aligned.m16n8k16.row.col.f32.f16.f16.f32 "
        "{%0, %1, %2, %3}, {%4, %5, %6, %7}, {%8, %9}, {%0, %1, %2, %3};"
        : "+f"(d[0]), "+f"(d[1]), "+f"(d[2]), "+f"(d[3])
        : "r"(a[0]), "r"(a[1]), "r"(a[2]), "r"(a[3]), "r"(b[0]), "r"(b[1]));
}

DINL uint32_t swz(uint32_t off) { return off ^ ((off >> 3) & 0x70); }   // 16B-chunk xor row%8

DINL float sigm_(float x) { return __fdividef(1.0f, 1.0f + __expf(-x)); }
DINL float tanh_(float x) { return 1.0f - __fdividef(2.0f, __expf(2.0f * x) + 1.0f); }

// ---------------- prep: weights (gate-interleave) + activations -> fp16 ----------------
#define WCHUNKS (NCOLS * KTOT / 8)      // 262144 8-half chunks
#define ACHUNKS (BATCH * KTOT / 8)      // 1048576
#define PREP_BLOCKS ((WCHUNKS + ACHUNKS) / 256)   // 5120

__global__ void __launch_bounds__(256) prep_kernel(
    const float* __restrict__ x, const float* __restrict__ h,
    const float* __restrict__ Wfx, const float* __restrict__ Wfh,
    const float* __restrict__ Wix, const float* __restrict__ Wih,
    const float* __restrict__ Wgx, const float* __restrict__ Wgh,
    const float* __restrict__ Wox, const float* __restrict__ Woh,
    const float* __restrict__ bfx, const float* __restrict__ bfh,
    const float* __restrict__ bix, const float* __restrict__ bih,
    const float* __restrict__ bgx, const float* __restrict__ bgh,
    const float* __restrict__ box_, const float* __restrict__ boh)
{
    const size_t q = (size_t)blockIdx.x * 256 + threadIdx.x;
    const float* s;
    __half* dst;
    if (q < WCHUNKS) {
        const int n = (int)(q >> 7), c = (int)(q & 127);   // row, 8-half chunk
        const int g = n & 3, j = n >> 2;
        const float *wx, *wh, *bx, *bh;
        if      (g == 0) { wx = Wfx; wh = Wfh; bx = bfx;  bh = bfh; }
        else if (g == 1) { wx = Wix; wh = Wih; bx = bix;  bh = bih; }
        else if (g == 2) { wx = Wgx; wh = Wgh; bx = bgx;  bh = bgh; }
        else             { wx = Wox; wh = Woh; bx = box_; bh = boh; }
        s = (c < 64) ? (wx + (size_t)j * 512 + c * 8)
                     : (wh + (size_t)j * 512 + (c - 64) * 8);
        dst = g_Bph + q * 8;
        if (c == 0) g_bias[n] = bx[j] + bh[j];
    } else {
        const size_t qa = q - WCHUNKS;
        const int row = (int)(qa >> 7), c = (int)(qa & 127);
        s = (c < 64) ? (x + (size_t)row * 512 + c * 8)
                     : (h + (size_t)row * 512 + (c - 64) * 8);
        dst = g_Ah + qa * 8;
    }
    const float4 v0 = *(const float4*)(s);
    const float4 v1 = *(const float4*)(s + 4);
    uint4 o;
    o.x = pack_h2(v0.x, v0.y);
    o.y = pack_h2(v0.z, v0.w);
    o.z = pack_h2(v1.x, v1.y);
    o.w = pack_h2(v1.z, v1.w);
    *(uint4*)dst = o;
}

// ---------------- stage loaders (both via cp.async) ----------------
DINL void cp_A(uint32_t sb, int it, int m0, int tid)
{
    const uint32_t a_st = sb + SMEM_A + (it % STAGES) * A_ST_BYTES;
    const int kg = it * BK;
    #pragma unroll
    for (int i = 0; i < 4; i++) {
        const int q = tid + i * THREADS;     // 0..1023 (128 rows x 8 chunks)
        const int r = q >> 3, c = q & 7;
        const uint32_t d = a_st + swz((uint32_t)(r * 128 + c * 16));
        cp_async16(d, g_Ah + (size_t)(m0 + r) * KTOT + kg + c * 8);
    }
}
DINL void cp_B(uint32_t sb, int it, int n0, int tid)
{
    const uint32_t b_st = sb + SMEM_B + (it % STAGES) * B_ST_BYTES;
    const int kg = it * BK;
    #pragma unroll
    for (int i = 0; i < 4; i++) {
        const int q = tid + i * THREADS;     // 0..1023
        const int r = q >> 3, c = q & 7;
        const uint32_t d = b_st + swz((uint32_t)(r * 128 + c * 16));
        cp_async16(d, g_Bph + (size_t)(n0 + r) * KTOT + kg + c * 8);
    }
}

// ---------------- main fused kernel: 8 warps, warp tile 64x32, occ 2 ----------------
__global__ void __launch_bounds__(THREADS, 2) lstm_mma_kernel(
    const float* __restrict__ c_tm1, float* __restrict__ out)
{
    extern __shared__ __align__(1024) char smem[];
    const uint32_t sb = smem_u32(smem);
    const int tid  = threadIdx.x;
    const int lane = tid & 31, wid = tid >> 5;
    const int m0 = blockIdx.y * BM;
    const int n0 = blockIdx.x * BN;
    const int wm = wid >> 2, wn = wid & 3;   // warp grid 2(M) x 4(N), warp tile 64x32

    float* bias_s = (float*)(smem + SMEM_BIAS);
    if (tid < BN) bias_s[tid] = g_bias[n0 + tid];

    // warm L2 with this tile's c_tm1 (one 128B line per row; epilogue tail killer)
    if (tid < BM) prefetch_l2(c_tm1 + (size_t)(m0 + tid) * HID + (n0 >> 2));

    // ldmatrix per-lane patterns (layouts verified in R12/R13).
    const int sub = lane >> 3, ri = lane & 7;
    const int arow = (sub & 1) * 8 + ri;
    const int achk = sub >> 1;               // 16B chunk within a k16 slice
    const int brow = (sub >> 1) * 8 + ri;
    const int bchk = sub & 1;

    float acc[4][4][4];
    #pragma unroll
    for (int a = 0; a < 4; a++)
        #pragma unroll
        for (int b = 0; b < 4; b++)
            #pragma unroll
            for (int c = 0; c < 4; c++) acc[a][b][c] = 0.0f;

    // prologue: stages 0,1 via cp.async
    cp_A(sb, 0, m0, tid); cp_B(sb, 0, n0, tid); cp_commit();
    cp_A(sb, 1, m0, tid); cp_B(sb, 1, n0, tid); cp_commit();

    for (int it = 0; it < KITERS; ++it) {
        cp_wait<1>();
        __syncthreads();                  // A(it)+B(it) resident & visible

        const uint32_t a_st = sb + SMEM_A + (it % STAGES) * A_ST_BYTES;
        const uint32_t b_st = sb + SMEM_B + (it % STAGES) * B_ST_BYTES;

        // ks=0 LDSM addresses; per-ks address = addr0 ^ (ks<<5).
        uint32_t aaddr0[4], baddr0[2];
        #pragma unroll
        for (int mt = 0; mt < 4; mt++) {
            const int row = wm * 64 + mt * 16 + arow;
            aaddr0[mt] = a_st + (uint32_t)row * 128 +
                         ((uint32_t)(achk ^ (row & 7)) << 4);
        }
        #pragma unroll
        for (int nt2 = 0; nt2 < 2; nt2++) {
            const int row = wn * 32 + nt2 * 16 + brow;
            baddr0[nt2] = b_st + (uint32_t)row * 128 +
                          ((uint32_t)(bchk ^ (row & 7)) << 4);
        }

        #pragma unroll
        for (int ks = 0; ks < 4; ks++) {  // 4 x k16 = BK=64
            const uint32_t kx = (uint32_t)ks << 5;
            uint32_t af[4][4], bf[4][2];
            #pragma unroll
            for (int mt = 0; mt < 4; mt++)
                ldsm4(aaddr0[mt] ^ kx, af[mt]);
            #pragma unroll
            for (int nt2 = 0; nt2 < 2; nt2++) {
                uint32_t t[4];
                ldsm4(baddr0[nt2] ^ kx, t);
                bf[nt2 * 2][0] = t[0]; bf[nt2 * 2][1] = t[1];
                bf[nt2 * 2 + 1][0] = t[2]; bf[nt2 * 2 + 1][1] = t[3];
            }
            if (ks == 0) {
                // issue next-stage copies inside the LDSM->MMA dependency window
                if (it + 2 < KITERS) { cp_A(sb, it + 2, m0, tid); cp_B(sb, it + 2, n0, tid); }
                cp_commit();          // one group per iteration (possibly empty)
            }
            #pragma unroll
            for (int mt = 0; mt < 4; mt++)
                #pragma unroll
                for (int nt = 0; nt < 4; nt++)
                    mma16(acc[mt][nt], af[mt], bf[nt]);
        }
    }

    // -------- fused LSTM epilogue on register accumulators --------
    // c-frag: c0,c1 = (row g, cols 2*t4, 2*t4+1); c2,c3 = (row g+8, same cols).
    // Gate-interleaved cols: even t4 holds (f,i), odd t4 holds (g,o) of the same j;
    // lane^1 exchange gives each lane all 4 gates. Even lane stores h_t, odd stores c_t.
    float* h_out = out;
    float* c_out = out + (size_t)BATCH * HID;
    const int t4 = lane & 3, g = lane >> 2;
    const bool even = (t4 & 1) == 0;

    #pragma unroll
    for (int mt = 0; mt < 4; ++mt) {
        const int r1 = m0 + wm * 64 + mt * 16 + g;
        const int r2 = r1 + 8;
        #pragma unroll
        for (int nt = 0; nt < 4; ++nt) {
            const int nl = wn * 32 + nt * 8;
            const int col0 = nl + 2 * t4;
            const float p0 = acc[mt][nt][0] + bias_s[col0];
            const float p1 = acc[mt][nt][1] + bias_s[col0 + 1];
            const float p2 = acc[mt][nt][2] + bias_s[col0];
            const float p3 = acc[mt][nt][3] + bias_s[col0 + 1];
            const float q0 = __shfl_xor_sync(0xffffffffu, p0, 1);
            const float q1 = __shfl_xor_sync(0xffffffffu, p1, 1);
            const float q2 = __shfl_xor_sync(0xffffffffu, p2, 1);
            const float q3 = __shfl_xor_sync(0xffffffffu, p3, 1);
            const float fr1 = even ? p0 : q0, ir1 = even ? p1 : q1;
            const float gr1 = even ? q0 : p0, or1 = even ? q1 : p1;
            const float fr2 = even ? p2 : q2, ir2 = even ? p3 : q3;
            const float gr2 = even ? q2 : p2, or2 = even ? q3 : p3;

            const int j = (n0 + nl + ((t4 >> 1) << 2)) >> 2;
            const float cp1 = c_tm1[(size_t)r1 * HID + j];
            const float cp2 = c_tm1[(size_t)r2 * HID + j];
            const float cn1 = sigm_(fr1) * cp1 + sigm_(ir1) * tanh_(gr1);
            const float cn2 = sigm_(fr2) * cp2 + sigm_(ir2) * tanh_(gr2);
            const float hn1 = sigm_(or1) * tanh_(cn1);
            const float hn2 = sigm_(or2) * tanh_(cn2);
            if (even) {
                h_out[(size_t)r1 * HID + j] = hn1;
                h_out[(size_t)r2 * HID + j] = hn2;
            } else {
                c_out[(size_t)r1 * HID + j] = cn1;
                c_out[(size_t)r2 * HID + j] = cn2;
            }
        }
    }
}

// ---------------- launcher ----------------
extern "C" void kernel_launch(void* const* d_in, const int* in_sizes, int n_in,
                              void* d_out, int out_size)
{
    const float* x    = (const float*)d_in[0];
    const float* h    = (const float*)d_in[1];
    const float* c    = (const float*)d_in[2];
    const float* Wfx  = (const float*)d_in[3];
    const float* bfx  = (const float*)d_in[4];
    const float* Wfh  = (const float*)d_in[5];
    const float* bfh  = (const float*)d_in[6];
    const float* Wix  = (const float*)d_in[7];
    const float* bix  = (const float*)d_in[8];
    const float* Wih  = (const float*)d_in[9];
    const float* bih  = (const float*)d_in[10];
    const float* Wgx  = (const float*)d_in[11];
    const float* bgx  = (const float*)d_in[12];
    const float* Wgh  = (const float*)d_in[13];
    const float* bgh  = (const float*)d_in[14];
    const float* Wox  = (const float*)d_in[15];
    const float* box_ = (const float*)d_in[16];
    const float* Woh  = (const float*)d_in[17];
    const float* boh  = (const float*)d_in[18];

    cudaFuncSetAttribute(lstm_mma_kernel,
                         cudaFuncAttributeMaxDynamicSharedMemorySize, SMEM_TOTAL);

    prep_kernel<<<PREP_BLOCKS, 256>>>(x, h,
                                      Wfx, Wfh, Wix, Wih, Wgx, Wgh, Wox, Woh,
                                      bfx, bfh, bix, bih, bgx, bgh, box_, boh);

    dim3 grid(NCOLS / BN, BATCH / BM);   // (16, 64)
    lstm_mma_kernel<<<grid, THREADS, SMEM_TOTAL>>>(c, (float*)d_out);
}